// round 1
// baseline (speedup 1.0000x reference)
#include <cuda_runtime.h>

#define NMAX 100000
#define EMAX 1600000
#define HD 64

// Scratch (device globals — allocation-free per harness rules)
__device__ float g_deg[NMAX];          // degree, then dinv (in place)
__device__ float g_hw [NMAX * HD];     // h @ W (per layer, reused)
__device__ float g_h1 [NMAX * HD];     // post-relu layer-1 output
__device__ float g_acc1[NMAX * HD];    // scatter accumulator layer 1
__device__ float g_acc2[NMAX * HD];    // scatter accumulator layer 2
__device__ float g_pool[HD];           // feature sums for mean pool

// ---------------------------------------------------------------------------
// init: zero accumulators + pool, deg = 1.0 (self-loop weight)
__global__ void k_init(int n) {
    int i = blockIdx.x * blockDim.x + threadIdx.x;
    int stride = gridDim.x * blockDim.x;
    int tot = n * HD;
    for (int j = i; j < tot; j += stride) { g_acc1[j] = 0.f; g_acc2[j] = 0.f; }
    for (int j = i; j < n;   j += stride) g_deg[j] = 1.0f;
    if (i < HD) g_pool[i] = 0.f;
}

// deg[row[e]] += attr[e]
__global__ void k_deg(const int* __restrict__ rowp, const float* __restrict__ attr, int e) {
    int i = blockIdx.x * blockDim.x + threadIdx.x;
    if (i < e) atomicAdd(&g_deg[rowp[i]], attr[i]);
}

// dinv = rsqrt(deg)  (deg >= 1 always)
__global__ void k_dinv(int n) {
    int i = blockIdx.x * blockDim.x + threadIdx.x;
    if (i < n) g_deg[i] = rsqrtf(g_deg[i]);
}

// ---------------------------------------------------------------------------
// GEMM: g_hw = in @ W   (in: [n,64], W: [64,64])
// block = 256 threads, 64 rows per block; each thread computes 16 outputs
__global__ void k_gemm(const float* __restrict__ inp, const float* __restrict__ W,
                       int use_h1, int n) {
    __shared__ float sW[64 * 64];
    __shared__ float sX[64 * 65];
    const float* in = use_h1 ? g_h1 : inp;
    int tid = threadIdx.x;
    for (int j = tid; j < 64 * 64; j += 256) sW[j] = W[j];
    int rowBase = blockIdx.x * 64;
    for (int j = tid; j < 64 * 64; j += 256) {
        int r = j >> 6, c = j & 63;
        int gr = rowBase + r;
        sX[r * 65 + c] = (gr < n) ? in[(size_t)gr * 64 + c] : 0.f;
    }
    __syncthreads();
    int r  = tid >> 2;
    int c0 = (tid & 3) * 16;
    float acc[16];
#pragma unroll
    for (int q = 0; q < 16; q++) acc[q] = 0.f;
#pragma unroll
    for (int k = 0; k < 64; k++) {
        float a = sX[r * 65 + k];
#pragma unroll
        for (int q = 0; q < 16; q++) acc[q] += a * sW[k * 64 + c0 + q];
    }
    int gr = rowBase + r;
    if (gr < n) {
#pragma unroll
        for (int q = 0; q < 16; q += 4)
            *(float4*)&g_hw[(size_t)gr * 64 + c0 + q] =
                make_float4(acc[q], acc[q + 1], acc[q + 2], acc[q + 3]);
    }
}

// ---------------------------------------------------------------------------
// Edge scatter: acc[row] += norm * hw[col]   (norm = dinv[row]*attr*dinv[col])
// 64 edges per block; 16 threads per edge, float4 per thread; vector red.
#define EPB 64
__global__ void k_scatter(const int* __restrict__ rowp, const int* __restrict__ colp,
                          const float* __restrict__ attr, int which, int e) {
    __shared__ int   s_row[EPB];
    __shared__ int   s_col[EPB];
    __shared__ float s_nrm[EPB];
    float* acc = which ? g_acc2 : g_acc1;
    int tid = threadIdx.x;
    int base = blockIdx.x * EPB;
    if (tid < EPB) {
        int ei = base + tid;
        if (ei < e) {
            int r = rowp[ei], c = colp[ei];
            s_row[tid] = r;
            s_col[tid] = c;
            s_nrm[tid] = g_deg[r] * attr[ei] * g_deg[c];
        } else {
            s_row[tid] = -1;
        }
    }
    __syncthreads();
    int g = tid >> 4, t = tid & 15;
#pragma unroll
    for (int it = 0; it < 4; it++) {
        int li = g + it * 16;
        int r = s_row[li];
        if (r < 0) continue;
        float nrm = s_nrm[li];
        const float4 v = *(const float4*)&g_hw[(size_t)s_col[li] * 64 + t * 4];
        float* dst = &acc[(size_t)r * 64 + t * 4];
        asm volatile("red.global.add.v4.f32 [%0], {%1,%2,%3,%4};"
                     :: "l"(dst), "f"(v.x * nrm), "f"(v.y * nrm),
                        "f"(v.z * nrm), "f"(v.w * nrm)
                     : "memory");
    }
}

// ---------------------------------------------------------------------------
// layer-1 epilogue: h1 = relu(acc1 + dinv^2 * hw + b1)
__global__ void k_post1(const float* __restrict__ bias, int n) {
    int idx = blockIdx.x * blockDim.x + threadIdx.x;  // one float4 per thread
    if (idx >= n * 16) return;
    int i = idx >> 4, q = idx & 15;
    float d = g_deg[i];
    float sl = d * d;
    float4 a  = *(const float4*)&g_acc1[(size_t)idx * 4];
    float4 hv = *(const float4*)&g_hw [(size_t)idx * 4];
    float4 b  = *(const float4*)&bias[q * 4];
    float4 r;
    r.x = fmaxf(a.x + sl * hv.x + b.x, 0.f);
    r.y = fmaxf(a.y + sl * hv.y + b.y, 0.f);
    r.z = fmaxf(a.z + sl * hv.z + b.z, 0.f);
    r.w = fmaxf(a.w + sl * hv.w + b.w, 0.f);
    *(float4*)&g_h1[(size_t)idx * 4] = r;
}

// layer-2 epilogue fused with mean-pool accumulation
// block handles 1024 nodes; thread (q = tid&15 feature-quad, r = tid>>4 node lane)
__global__ void k_post2_pool(const float* __restrict__ bias, int n) {
    __shared__ float4 sbuf[256];
    int tid = threadIdx.x;
    int q = tid & 15, r = tid >> 4;
    float4 b = *(const float4*)&bias[q * 4];
    float4 sum = make_float4(0.f, 0.f, 0.f, 0.f);
    int base = blockIdx.x * 1024;
#pragma unroll 4
    for (int it = 0; it < 64; it++) {
        int i = base + r + (it << 4);
        if (i >= n) break;
        float d = g_deg[i];
        float sl = d * d;
        const float4 a  = *(const float4*)&g_acc2[(size_t)i * 64 + q * 4];
        const float4 hv = *(const float4*)&g_hw [(size_t)i * 64 + q * 4];
        sum.x += fmaxf(a.x + sl * hv.x + b.x, 0.f);
        sum.y += fmaxf(a.y + sl * hv.y + b.y, 0.f);
        sum.z += fmaxf(a.z + sl * hv.z + b.z, 0.f);
        sum.w += fmaxf(a.w + sl * hv.w + b.w, 0.f);
    }
    sbuf[tid] = sum;
    __syncthreads();
    if (r == 0) {
        float4 tot = sbuf[q];
#pragma unroll
        for (int j = 1; j < 16; j++) {
            float4 v = sbuf[q + 16 * j];
            tot.x += v.x; tot.y += v.y; tot.z += v.z; tot.w += v.w;
        }
        float* dst = &g_pool[q * 4];
        asm volatile("red.global.add.v4.f32 [%0], {%1,%2,%3,%4};"
                     :: "l"(dst), "f"(tot.x), "f"(tot.y), "f"(tot.z), "f"(tot.w)
                     : "memory");
    }
}

// ---------------------------------------------------------------------------
// head: z = [pool/n, h_other];  out = relu(z@Wc1+bc1) @ Wc2 + bc2
__global__ void k_head(const float* __restrict__ Wc1, const float* __restrict__ bc1,
                       const float* __restrict__ Wc2, const float* __restrict__ bc2,
                       const float* __restrict__ h_other, float* __restrict__ out, int n) {
    __shared__ float z[128];
    __shared__ float hid[64];
    int t = threadIdx.x;
    if (t < 64) {
        z[t]      = g_pool[t] / (float)n;
        z[64 + t] = h_other[t];
    }
    __syncthreads();
    if (t < 64) {
        float s = bc1[t];
#pragma unroll 8
        for (int i = 0; i < 128; i++) s += z[i] * Wc1[i * 64 + t];
        hid[t] = fmaxf(s, 0.f);
    }
    __syncthreads();
    if (t < 3) {
        float s = bc2[t];
#pragma unroll
        for (int j = 0; j < 64; j++) s += hid[j] * Wc2[j * 3 + t];
        out[t] = s;
    }
}

// ---------------------------------------------------------------------------
extern "C" void kernel_launch(void* const* d_in, const int* in_sizes, int n_in,
                              void* d_out, int out_size) {
    const float* x        = (const float*)d_in[0];
    const int*   eidx     = (const int*)  d_in[1];
    const float* eattr    = (const float*)d_in[2];
    // d_in[3] = batch (unused; single graph)
    const float* W1       = (const float*)d_in[4];
    const float* b1       = (const float*)d_in[5];
    const float* W2       = (const float*)d_in[6];
    const float* b2       = (const float*)d_in[7];
    const float* Wc1      = (const float*)d_in[8];
    const float* bc1      = (const float*)d_in[9];
    const float* Wc2      = (const float*)d_in[10];
    const float* bc2      = (const float*)d_in[11];
    const float* h_other  = (const float*)d_in[12];
    float* out = (float*)d_out;

    int n = in_sizes[0] / HD;      // nodes
    int e = in_sizes[2];           // edges
    const int* rowp = eidx;
    const int* colp = eidx + e;

    // 1) init scratch
    k_init<<<2048, 256>>>(n);
    // 2) degree + dinv
    k_deg<<<(e + 255) / 256, 256>>>(rowp, eattr, e);
    k_dinv<<<(n + 255) / 256, 256>>>(n);
    // 3) layer 1: gemm -> scatter -> relu
    k_gemm<<<(n + 63) / 64, 256>>>(x, W1, 0, n);
    k_scatter<<<(e + EPB - 1) / EPB, 256>>>(rowp, colp, eattr, 0, e);
    k_post1<<<(n * 16 + 255) / 256, 256>>>(b1, n);
    // 4) layer 2: gemm -> scatter -> relu + pool
    k_gemm<<<(n + 63) / 64, 256>>>(x, W2, 1, n);
    k_scatter<<<(e + EPB - 1) / EPB, 256>>>(rowp, colp, eattr, 1, e);
    k_post2_pool<<<(n + 1023) / 1024, 256>>>(b2, n);
    // 5) head
    k_head<<<1, 64>>>(Wc1, bc1, Wc2, bc2, h_other, out, n);
}